// round 8
// baseline (speedup 1.0000x reference)
#include <cuda_runtime.h>
#include <math.h>

// ---------------------------------------------------------------------------
// VQ-VAE forward, fp32 packed f32x2, register-A blocking (8px x 8oc), sm_103a
// ---------------------------------------------------------------------------

typedef unsigned long long u64;

__device__ __forceinline__ u64 bcast2(float v) {
    u64 r; asm("mov.b64 %0, {%1, %1};" : "=l"(r) : "f"(v)); return r;
}
__device__ __forceinline__ u64 pack2(float lo, float hi) {
    u64 r; asm("mov.b64 %0, {%1, %2};" : "=l"(r) : "f"(lo), "f"(hi)); return r;
}
__device__ __forceinline__ void fma2(u64& d, u64 a, u64 b) {
    asm("fma.rn.f32x2 %0, %1, %2, %0;" : "+l"(d) : "l"(a), "l"(b));
}
__device__ __forceinline__ float2 unpack2(u64 v) {
    float2 r; asm("mov.b64 {%0, %1}, %2;" : "=f"(r.x), "=f"(r.y) : "l"(v)); return r;
}

__device__ float g_big[67108864];            // 32*128*128*128
__device__ float g_z[8388608];               // 32*64*64*64 NHWC
__device__ float g_q[8388608];
__device__ float g_part[512];

// ===========================================================================
// conv1: x(32,3,256,256) * enc_w1(128,3,4,4) s2 p1 + b, ReLU -> z1 NCHW
// (unchanged from R6 pass)
// ===========================================================================
__global__ void __launch_bounds__(512) k_conv1(const float* __restrict__ x,
                                               const float* __restrict__ w,
                                               const float* __restrict__ b) {
    __shared__ __align__(16) float w_s[16 * 3 * 128];        // [tap][ic][oc]
    __shared__ __align__(16) float in_s[3 * 19 * 96];        // 5472
    const int n = blockIdx.z;
    const int Tx = blockIdx.x * 32, Ty = blockIdx.y * 8;
    const int tid = threadIdx.x;
    const int lane = tid & 31, wid = tid >> 5;
    const int ocg = wid >> 1, rw = wid & 1;
    const int oc16 = ocg * 16;

    {
        const float4* w4 = (const float4*)w;
        for (int i = tid; i < 1536; i += 512) {
            int t4 = i & 3, rest = i >> 2;
            int ic = rest % 3, oc = rest / 3;
            float4 v = w4[(oc * 3 + ic) * 4 + t4];
            int base = ((t4 * 4) * 3 + ic) * 128 + oc;
            w_s[base + 0 * 3 * 128] = v.x;
            w_s[base + 1 * 3 * 128] = v.y;
            w_s[base + 2 * 3 * 128] = v.z;
            w_s[base + 3 * 3 * 128] = v.w;
        }
    }
    const int iy0 = 2 * Ty - 1, ix0 = 2 * Tx - 1;
    for (int i = tid; i < 3 * 19 * 67; i += 512) {
        int ic = i / (19 * 67), r = i % (19 * 67);
        int row = r / 67, col = r % 67;
        int gy = iy0 + row, gx = ix0 + col;
        float v = 0.f;
        if (gy >= 0 && gy < 256 && gx >= 0 && gx < 256)
            v = x[((n * 3 + ic) * 256 + gy) * 256 + gx];
        in_s[(ic * 19 + row) * 96 + (col & 1) * 48 + (col >> 1)] = v;
    }
    __syncthreads();

    u64 acc[4][8];
#pragma unroll
    for (int pp = 0; pp < 4; pp++)
#pragma unroll
        for (int k = 0; k < 8; k++) acc[pp][k] = 0ull;

    for (int ic = 0; ic < 3; ic++) {
#pragma unroll
        for (int ky = 0; ky < 4; ky++) {
#pragma unroll
            for (int kx = 0; kx < 4; kx++) {
                const ulonglong2* wp =
                    (const ulonglong2*)&w_s[((ky * 4 + kx) * 3 + ic) * 128 + oc16];
                ulonglong2 w0 = wp[0], w1 = wp[1], w2 = wp[2], w3 = wp[3];
                int coff = (kx & 1) * 48 + lane + (kx >> 1);
#pragma unroll
                for (int pp = 0; pp < 4; pp++) {
                    int tr = 2 * rw + 4 * pp + ky;
                    u64 iv = bcast2(in_s[(ic * 19 + tr) * 96 + coff]);
                    fma2(acc[pp][0], iv, w0.x); fma2(acc[pp][1], iv, w0.y);
                    fma2(acc[pp][2], iv, w1.x); fma2(acc[pp][3], iv, w1.y);
                    fma2(acc[pp][4], iv, w2.x); fma2(acc[pp][5], iv, w2.y);
                    fma2(acc[pp][6], iv, w3.x); fma2(acc[pp][7], iv, w3.y);
                }
            }
        }
    }
    const int ox = Tx + lane;
#pragma unroll
    for (int pp = 0; pp < 4; pp++) {
        int oy = Ty + rw + 2 * pp;
#pragma unroll
        for (int k = 0; k < 8; k++) {
            float2 v = unpack2(acc[pp][k]);
            int oc = oc16 + 2 * k;
            g_big[((n * 128 + oc) * 128 + oy) * 128 + ox]     = fmaxf(v.x + b[oc], 0.f);
            g_big[((n * 128 + oc + 1) * 128 + oy) * 128 + ox] = fmaxf(v.y + b[oc + 1], 0.f);
        }
    }
}

// ===========================================================================
// conv2 v2: z1 NCHW * enc_w2(64,128,4,4) s2 p1 + b -> g_z NHWC
// tile 32 cols x 16 rows, grid (2,4,32), block 512.
// warp = output row r (0..15); lane = t(0..3)*8+og: 8 px (ox=Tx+8t+j), 8 oc.
// A loaded as 12-float registers per (ic,row,parity); compile-time picks.
// ===========================================================================
__global__ void __launch_bounds__(512) k_conv2(const float* __restrict__ w,
                                               const float* __restrict__ b) {
    extern __shared__ float sm[];
    float* in_s = sm;            // 4*35*96 = 13440
    float* w_s = sm + 13440;     // 16*4*64 = 4096
    const int n = blockIdx.z;
    const int Tx = blockIdx.x * 32, Ty = blockIdx.y * 16;
    const int tid = threadIdx.x;
    const int lane = tid & 31;
    const int r = tid >> 5;                 // output row 0..15
    const int og = lane & 7, t = lane >> 3; // oc group, px octet
    const int ocb = og * 8;
    const int iy0 = 2 * Ty - 1, ix0 = 2 * Tx - 1;

    float bia[8];
    {
        const float4* b4 = (const float4*)(b + ocb);
        float4 b0 = b4[0], b1 = b4[1];
        bia[0]=b0.x; bia[1]=b0.y; bia[2]=b0.z; bia[3]=b0.w;
        bia[4]=b1.x; bia[5]=b1.y; bia[6]=b1.z; bia[7]=b1.w;
    }

    u64 acc[8][4];
#pragma unroll
    for (int j = 0; j < 8; j++)
#pragma unroll
        for (int k = 0; k < 4; k++) acc[j][k] = 0ull;

    const float4* w4 = (const float4*)w;
    for (int cc = 0; cc < 32; cc++) {
        __syncthreads();
        for (int i = tid; i < 1024; i += 512) {
            int t4 = i & 3, ic4 = (i >> 2) & 3, oc = i >> 4;
            float4 v = w4[(oc * 128 + cc * 4 + ic4) * 4 + t4];
            int base = ((t4 * 4) * 4 + ic4) * 64 + oc;
            w_s[base + 0 * 4 * 64] = v.x;
            w_s[base + 1 * 4 * 64] = v.y;
            w_s[base + 2 * 4 * 64] = v.z;
            w_s[base + 3 * 4 * 64] = v.w;
        }
        for (int i = tid; i < 4 * 35 * 67; i += 512) {
            int ic4 = i / (35 * 67), rr = i % (35 * 67);
            int row = rr / 67, col = rr % 67;
            int gy = iy0 + row, gx = ix0 + col;
            float v = 0.f;
            if (gy >= 0 && gy < 128 && gx >= 0 && gx < 128)
                v = g_big[((n * 128 + cc * 4 + ic4) * 128 + gy) * 128 + gx];
            in_s[(ic4 * 35 + row) * 96 + (col & 1) * 48 + (col >> 1)] = v;
        }
        __syncthreads();

        for (int ic4 = 0; ic4 < 4; ic4++) {
#pragma unroll
            for (int ky = 0; ky < 4; ky++) {
                int row = 2 * r + ky;
                int base = (ic4 * 35 + row) * 96 + 8 * t;
                const float4* pe = (const float4*)&in_s[base];
                const float4* po = (const float4*)&in_s[base + 48];
                float4 E0 = pe[0], E1 = pe[1], E2 = pe[2];
                float4 O0 = po[0], O1 = po[1], O2 = po[2];
                float e[12], o[12];
                e[0]=E0.x; e[1]=E0.y; e[2]=E0.z; e[3]=E0.w;
                e[4]=E1.x; e[5]=E1.y; e[6]=E1.z; e[7]=E1.w;
                e[8]=E2.x; e[9]=E2.y; e[10]=E2.z; e[11]=E2.w;
                o[0]=O0.x; o[1]=O0.y; o[2]=O0.z; o[3]=O0.w;
                o[4]=O1.x; o[5]=O1.y; o[6]=O1.z; o[7]=O1.w;
                o[8]=O2.x; o[9]=O2.y; o[10]=O2.z; o[11]=O2.w;
#pragma unroll
                for (int kx = 0; kx < 4; kx++) {
                    const int sh = kx >> 1;
                    const float4* wp =
                        (const float4*)&w_s[((ky * 4 + kx) * 4 + ic4) * 64 + ocb];
                    float4 wa = wp[0], wb = wp[1];
                    u64 W0 = pack2(wa.x, wa.y), W1 = pack2(wa.z, wa.w);
                    u64 W2 = pack2(wb.x, wb.y), W3 = pack2(wb.z, wb.w);
#pragma unroll
                    for (int j = 0; j < 8; j++) {
                        float av = (kx & 1) ? o[j + sh] : e[j + sh];
                        u64 a2 = bcast2(av);
                        fma2(acc[j][0], a2, W0); fma2(acc[j][1], a2, W1);
                        fma2(acc[j][2], a2, W2); fma2(acc[j][3], a2, W3);
                    }
                }
            }
        }
    }
    const int oy = Ty + r;
#pragma unroll
    for (int j = 0; j < 8; j++) {
        int ox = Tx + 8 * t + j;
        float4* zp = (float4*)&g_z[((n * 64 + oy) * 64 + ox) * 64 + ocb];
        float2 p0 = unpack2(acc[j][0]), p1 = unpack2(acc[j][1]);
        float2 p2 = unpack2(acc[j][2]), p3 = unpack2(acc[j][3]);
        float4 v0, v1;
        v0.x = p0.x + bia[0]; v0.y = p0.y + bia[1];
        v0.z = p1.x + bia[2]; v0.w = p1.y + bia[3];
        v1.x = p2.x + bia[4]; v1.y = p2.y + bia[5];
        v1.z = p3.x + bia[6]; v1.w = p3.y + bia[7];
        zp[0] = v0; zp[1] = v1;
    }
}

// ===========================================================================
// VQ (unchanged from R6 pass)
// ===========================================================================
__global__ void __launch_bounds__(256) k_vq(const float* __restrict__ cb) {
    extern __shared__ float sm[];
    float* cb_s = sm;               // 512*64
    float* ccn = sm + 32768;        // 512
    float* red = ccn + 512;         // 256
    const int tid = threadIdx.x;

    for (int i = tid; i < 32768; i += 256) cb_s[i] = cb[i];
    __syncthreads();
    for (int j = tid; j < 512; j += 256) {
        float s = 0.f;
        const float* cp = &cb_s[j * 64];
        for (int d = 0; d < 64; d++) s = fmaf(cp[d], cp[d], s);
        ccn[j] = s;
    }
    __syncthreads();

    const int i = blockIdx.x * 256 + tid;
    u64 zr[32];
    {
        const ulonglong2* zp = (const ulonglong2*)&g_z[(size_t)i * 64];
#pragma unroll
        for (int d = 0; d < 16; d++) {
            ulonglong2 tt = zp[d];
            zr[2 * d] = tt.x; zr[2 * d + 1] = tt.y;
        }
    }

    float best = 3.4e38f;
    int bi = 0;
    for (int j = 0; j < 512; j++) {
        const ulonglong2* cp = (const ulonglong2*)&cb_s[j * 64];
        u64 s2 = 0ull;
#pragma unroll
        for (int d = 0; d < 16; d++) {
            ulonglong2 c = cp[d];
            fma2(s2, zr[2 * d], c.x);
            fma2(s2, zr[2 * d + 1], c.y);
        }
        float2 ss = unpack2(s2);
        float score = ccn[j] - 2.f * (ss.x + ss.y);
        if (score < best) { best = score; bi = j; }
    }

    float4* qp = (float4*)&g_q[(size_t)i * 64];
    const float4* cp4 = (const float4*)&cb_s[bi * 64];
    const float4* zp4 = (const float4*)&g_z[(size_t)i * 64];
    float sq = 0.f;
#pragma unroll
    for (int d = 0; d < 16; d++) {
        float4 c = cp4[d], z = zp4[d];
        qp[d] = c;
        float dx = c.x - z.x, dy = c.y - z.y;
        float dz = c.z - z.z, dw = c.w - z.w;
        sq += dx * dx + dy * dy + dz * dz + dw * dw;
    }
    red[tid] = sq;
    __syncthreads();
    for (int st = 128; st > 0; st >>= 1) {
        if (tid < st) red[tid] += red[tid + st];
        __syncthreads();
    }
    if (tid == 0) g_part[blockIdx.x] = red[0];
}

// ===========================================================================
// deconv1 v2: q NHWC ^T-conv dec_w1(64,128,4,4) s2 p1 + b, ReLU -> h NHWC
// tile 32 cols x 8 rows, grid (4,16,32), block 512.
// warp = (r 0..7, h 0..1); lane = po(0..3)*8+og: c=po&1, t=po>>1.
// thread: 8 px (ox = Tx + c + 16t + 2j) x 8 oc (h*64+og*8).
// input stored in 2 parity-shifted planes: plane p, col' = col - p, stride 20.
// ===========================================================================
__global__ void __launch_bounds__(512) k_deconv1(const float* __restrict__ w,
                                                 const float* __restrict__ b) {
    extern __shared__ float sm[];
    float* in2 = sm;             // 2*8*6*20 = 1920
    float* w_s = sm + 1920;      // 16*1060 = 16960
    const int n = blockIdx.z;
    const int Tx = blockIdx.x * 32, Ty = blockIdx.y * 8;
    const int tid = threadIdx.x;
    const int lane = tid & 31, wid = tid >> 5;
    const int r = wid & 7, h = wid >> 3;
    const int og = lane & 7, po = lane >> 3;
    const int c = po & 1, t = po >> 1;
    const int ocb = h * 64 + og * 8;

    const int oy = Ty + r;
    const int ky0 = (r + 1) & 1;
    const int fl = (r + 1) >> 1;            // floor((r+1)/2), in 0..4
    const int kx0 = (c + 1) & 1;
    const int y0 = (Ty >> 1) - 1, x0 = (Tx >> 1) - 1;

    float bia[8];
    {
        const float4* b4 = (const float4*)(b + ocb);
        float4 b0 = b4[0], b1 = b4[1];
        bia[0]=b0.x; bia[1]=b0.y; bia[2]=b0.z; bia[3]=b0.w;
        bia[4]=b1.x; bia[5]=b1.y; bia[6]=b1.z; bia[7]=b1.w;
    }

    u64 acc[8][4];
#pragma unroll
    for (int j = 0; j < 8; j++)
#pragma unroll
        for (int k = 0; k < 4; k++) acc[j][k] = 0ull;

    const int abase0 = c * 960 + 8 * t;     // + ic8*120 + row*20

    const float4* w4 = (const float4*)w;
    for (int cc = 0; cc < 8; cc++) {
        __syncthreads();
        // weights: w_s[tap*1060 + ic8*132 + oc] = w[((cc*8+ic8)*128+oc)*16+tap]
        for (int i = tid; i < 4096; i += 512) {
            int t4 = i & 3, oc = (i >> 2) & 127, ic8 = i >> 9;
            float4 v = w4[((cc * 8 + ic8) * 128 + oc) * 4 + t4];
            int base = (t4 * 4) * 1060 + ic8 * 132 + oc;
            w_s[base + 0 * 1060] = v.x;
            w_s[base + 1 * 1060] = v.y;
            w_s[base + 2 * 1060] = v.z;
            w_s[base + 3 * 1060] = v.w;
        }
        // input: two parity-shifted planes [p][ic8][row][col'], col = col' + p
        for (int i = tid; i < 1920; i += 512) {
            int p = i / 960, rem = i % 960;
            int ic8 = rem / 120, rem2 = rem % 120;
            int row = rem2 / 20, colp = rem2 % 20;
            int col = colp + p;
            int gy = y0 + row, gx = x0 + col;
            float v = 0.f;
            if (col <= 17 && gy >= 0 && gy < 64 && gx >= 0 && gx < 64)
                v = g_q[(((size_t)n * 64 + gy) * 64 + gx) * 64 + cc * 8 + ic8];
            in2[i] = v;
        }
        __syncthreads();

        for (int ic8 = 0; ic8 < 8; ic8++) {
            // A windows: row fl+1 (ty=0) and row fl (ty=1), 12 floats each
            const float4* a0p = (const float4*)&in2[abase0 + ic8 * 120 + (fl + 1) * 20];
            const float4* a1p = (const float4*)&in2[abase0 + ic8 * 120 + fl * 20];
            float4 A0 = a0p[0], A1 = a0p[1], A2 = a0p[2];
            float4 B0 = a1p[0], B1 = a1p[1], B2 = a1p[2];
            float ea[12], fa[12];
            ea[0]=A0.x; ea[1]=A0.y; ea[2]=A0.z; ea[3]=A0.w;
            ea[4]=A1.x; ea[5]=A1.y; ea[6]=A1.z; ea[7]=A1.w;
            ea[8]=A2.x; ea[9]=A2.y; ea[10]=A2.z; ea[11]=A2.w;
            fa[0]=B0.x; fa[1]=B0.y; fa[2]=B0.z; fa[3]=B0.w;
            fa[4]=B1.x; fa[5]=B1.y; fa[6]=B1.z; fa[7]=B1.w;
            fa[8]=B2.x; fa[9]=B2.y; fa[10]=B2.z; fa[11]=B2.w;
#pragma unroll
            for (int ty = 0; ty < 2; ty++) {
                int ky = ky0 + 2 * ty;
#pragma unroll
                for (int tx = 0; tx < 2; tx++) {
                    int kx = kx0 + 2 * tx;
                    const float4* wp =
                        (const float4*)&w_s[(ky * 4 + kx) * 1060 + ic8 * 132 + ocb];
                    float4 wa = wp[0], wb = wp[1];
                    u64 W0 = pack2(wa.x, wa.y), W1 = pack2(wa.z, wa.w);
                    u64 W2 = pack2(wb.x, wb.y), W3 = pack2(wb.z, wb.w);
#pragma unroll
                    for (int j = 0; j < 8; j++) {
                        float av = ty ? fa[j + 1 - tx] : ea[j + 1 - tx];
                        u64 a2 = bcast2(av);
                        fma2(acc[j][0], a2, W0); fma2(acc[j][1], a2, W1);
                        fma2(acc[j][2], a2, W2); fma2(acc[j][3], a2, W3);
                    }
                }
            }
        }
    }
#pragma unroll
    for (int j = 0; j < 8; j++) {
        int ox = Tx + c + 16 * t + 2 * j;
        float4* hp = (float4*)&g_big[(((size_t)n * 128 + oy) * 128 + ox) * 128 + ocb];
        float2 p0 = unpack2(acc[j][0]), p1 = unpack2(acc[j][1]);
        float2 p2 = unpack2(acc[j][2]), p3 = unpack2(acc[j][3]);
        float4 v0, v1;
        v0.x = fmaxf(p0.x + bia[0], 0.f); v0.y = fmaxf(p0.y + bia[1], 0.f);
        v0.z = fmaxf(p1.x + bia[2], 0.f); v0.w = fmaxf(p1.y + bia[3], 0.f);
        v1.x = fmaxf(p2.x + bia[4], 0.f); v1.y = fmaxf(p2.y + bia[5], 0.f);
        v1.z = fmaxf(p3.x + bia[6], 0.f); v1.w = fmaxf(p3.y + bia[7], 0.f);
        hp[0] = v0; hp[1] = v1;
    }
}

// ===========================================================================
// deconv2 (unchanged from R6 pass)
// ===========================================================================
__global__ void __launch_bounds__(256) k_deconv2(const float* __restrict__ w,
                                                 const float* __restrict__ b,
                                                 float* __restrict__ out) {
    extern __shared__ float sm[];
    float* in_s = sm;             // 180*132 = 23760
    float* w_s = sm + 23760;      // 6144
    const int n = blockIdx.z;
    const int Tx = blockIdx.x * 32, Ty = blockIdx.y * 16;
    const int tid = threadIdx.x;
    const int py = tid >> 4, px = tid & 15;
    const int oy = Ty + py, ox = Tx + px;
    const int y0 = (Ty >> 1) - 1, x0 = (Tx >> 1) - 1;

    {
        const float4* w4 = (const float4*)w;
        for (int i = tid; i < 1536; i += 256) {
            int t4 = i & 3, rest = i >> 2;
            int oc = rest % 3, ic = rest / 3;
            float4 v = w4[(ic * 3 + oc) * 4 + t4];
            int base = ((t4 * 4) * 3 + oc) * 128 + ic;
            w_s[base + 0 * 3 * 128] = v.x;
            w_s[base + 1 * 3 * 128] = v.y;
            w_s[base + 2 * 3 * 128] = v.z;
            w_s[base + 3 * 3 * 128] = v.w;
        }
    }
    for (int i = tid; i < 23040; i += 256) {
        int ic = i & 127, pos = i >> 7;
        int ly = pos / 18, lx = pos % 18;
        int gy = y0 + ly, gx = x0 + lx;
        float v = 0.f;
        if (gy >= 0 && gy < 128 && gx >= 0 && gx < 128)
            v = g_big[(((size_t)n * 128 + gy) * 128 + gx) * 128 + ic];
        in_s[pos * 132 + ic] = v;
    }
    __syncthreads();

    const int ky0 = (oy + 1) & 1, kx0 = (ox + 1) & 1;
    const int lyA = ((oy + 1 - ky0) >> 1) - y0;
    const int lxA = ((ox + 1 - kx0) >> 1) - x0;

    u64 a[2][3];
#pragma unroll
    for (int q = 0; q < 2; q++)
#pragma unroll
        for (int k = 0; k < 3; k++) a[q][k] = 0ull;

#pragma unroll
    for (int ty = 0; ty < 2; ty++) {
        int ky = ky0 + 2 * ty, ly = lyA - ty;
#pragma unroll
        for (int tx = 0; tx < 2; tx++) {
            int kx = kx0 + 2 * tx;
            const ulonglong2* ip0 = (const ulonglong2*)&in_s[(ly * 18 + lxA - tx) * 132];
            const ulonglong2* ip1 = (const ulonglong2*)&in_s[(ly * 18 + lxA + 8 - tx) * 132];
            const ulonglong2* w0 = (const ulonglong2*)&w_s[((ky * 4 + kx) * 3 + 0) * 128];
            const ulonglong2* w1 = (const ulonglong2*)&w_s[((ky * 4 + kx) * 3 + 1) * 128];
            const ulonglong2* w2 = (const ulonglong2*)&w_s[((ky * 4 + kx) * 3 + 2) * 128];
#pragma unroll 8
            for (int cI = 0; cI < 32; cI++) {
                ulonglong2 v0 = w0[cI], v1 = w1[cI], v2 = w2[cI];
                ulonglong2 i0 = ip0[cI], i1 = ip1[cI];
                fma2(a[0][0], i0.x, v0.x); fma2(a[0][0], i0.y, v0.y);
                fma2(a[0][1], i0.x, v1.x); fma2(a[0][1], i0.y, v1.y);
                fma2(a[0][2], i0.x, v2.x); fma2(a[0][2], i0.y, v2.y);
                fma2(a[1][0], i1.x, v0.x); fma2(a[1][0], i1.y, v0.y);
                fma2(a[1][1], i1.x, v1.x); fma2(a[1][1], i1.y, v1.y);
                fma2(a[1][2], i1.x, v2.x); fma2(a[1][2], i1.y, v2.y);
            }
        }
    }
#pragma unroll
    for (int q = 0; q < 2; q++) {
        int oxq = ox + 16 * q;
        float2 r0 = unpack2(a[q][0]), r1 = unpack2(a[q][1]), r2 = unpack2(a[q][2]);
        out[(((size_t)n * 3 + 0) * 256 + oy) * 256 + oxq] = tanhf(r0.x + r0.y + b[0]);
        out[(((size_t)n * 3 + 1) * 256 + oy) * 256 + oxq] = tanhf(r1.x + r1.y + b[1]);
        out[(((size_t)n * 3 + 2) * 256 + oy) * 256 + oxq] = tanhf(r2.x + r2.y + b[2]);
    }
}

// deterministic loss finalize: vq_loss = 1.25 * sum / (131072*64)
__global__ void k_loss(float* __restrict__ out, int out_size) {
    __shared__ float red[256];
    int tid = threadIdx.x;
    red[tid] = g_part[tid] + g_part[tid + 256];
    __syncthreads();
    for (int st = 128; st > 0; st >>= 1) {
        if (tid < st) red[tid] += red[tid + st];
        __syncthreads();
    }
    if (tid == 0) out[out_size - 1] = 1.25f * red[0] / 8388608.0f;
}

extern "C" void kernel_launch(void* const* d_in, const int* in_sizes, int n_in,
                              void* d_out, int out_size) {
    const float* x   = (const float*)d_in[0];
    const float* ew1 = (const float*)d_in[1];
    const float* eb1 = (const float*)d_in[2];
    const float* ew2 = (const float*)d_in[3];
    const float* eb2 = (const float*)d_in[4];
    const float* cb  = (const float*)d_in[5];
    const float* dw1 = (const float*)d_in[6];
    const float* db1 = (const float*)d_in[7];
    const float* dw2 = (const float*)d_in[8];
    const float* db2 = (const float*)d_in[9];
    float* out = (float*)d_out;

    const int smem_conv2   = (13440 + 4096) * 4;   // 70144
    const int smem_vq      = (32768 + 512 + 256) * 4;
    const int smem_deconv1 = (1920 + 16960) * 4;   // 75520
    const int smem_deconv2 = (23760 + 6144) * 4;

    cudaFuncSetAttribute(k_conv2, cudaFuncAttributeMaxDynamicSharedMemorySize, smem_conv2);
    cudaFuncSetAttribute(k_vq, cudaFuncAttributeMaxDynamicSharedMemorySize, smem_vq);
    cudaFuncSetAttribute(k_deconv1, cudaFuncAttributeMaxDynamicSharedMemorySize, smem_deconv1);
    cudaFuncSetAttribute(k_deconv2, cudaFuncAttributeMaxDynamicSharedMemorySize, smem_deconv2);

    k_conv1<<<dim3(4, 16, 32), 512>>>(x, ew1, eb1);
    k_conv2<<<dim3(2, 4, 32), 512, smem_conv2>>>(ew2, eb2);
    k_vq<<<512, 256, smem_vq>>>(cb);
    k_deconv1<<<dim3(4, 16, 32), 512, smem_deconv1>>>(dw1, db1);
    k_deconv2<<<dim3(8, 16, 32), 256, smem_deconv2>>>(dw2, db2, out);
    k_loss<<<1, 256>>>(out, out_size);
}

// round 9
// speedup vs baseline: 1.0013x; 1.0013x over previous
#include <cuda_runtime.h>
#include <math.h>

// ---------------------------------------------------------------------------
// VQ-VAE forward, fp32 packed f32x2, register-A blocking (8px x 8oc), sm_103a
// ---------------------------------------------------------------------------

typedef unsigned long long u64;

__device__ __forceinline__ u64 bcast2(float v) {
    u64 r; asm("mov.b64 %0, {%1, %1};" : "=l"(r) : "f"(v)); return r;
}
__device__ __forceinline__ u64 pack2(float lo, float hi) {
    u64 r; asm("mov.b64 %0, {%1, %2};" : "=l"(r) : "f"(lo), "f"(hi)); return r;
}
__device__ __forceinline__ void fma2(u64& d, u64 a, u64 b) {
    asm("fma.rn.f32x2 %0, %1, %2, %0;" : "+l"(d) : "l"(a), "l"(b));
}
__device__ __forceinline__ float2 unpack2(u64 v) {
    float2 r; asm("mov.b64 {%0, %1}, %2;" : "=f"(r.x), "=f"(r.y) : "l"(v)); return r;
}

__device__ float g_big[67108864];            // 32*128*128*128
__device__ float g_z[8388608];               // 32*64*64*64 NHWC
__device__ float g_q[8388608];
__device__ float g_part[512];

// ===========================================================================
// conv1: x(32,3,256,256) * enc_w1(128,3,4,4) s2 p1 + b, ReLU -> z1 NCHW
// (unchanged from R6 pass)
// ===========================================================================
__global__ void __launch_bounds__(512) k_conv1(const float* __restrict__ x,
                                               const float* __restrict__ w,
                                               const float* __restrict__ b) {
    __shared__ __align__(16) float w_s[16 * 3 * 128];        // [tap][ic][oc]
    __shared__ __align__(16) float in_s[3 * 19 * 96];        // 5472
    const int n = blockIdx.z;
    const int Tx = blockIdx.x * 32, Ty = blockIdx.y * 8;
    const int tid = threadIdx.x;
    const int lane = tid & 31, wid = tid >> 5;
    const int ocg = wid >> 1, rw = wid & 1;
    const int oc16 = ocg * 16;

    {
        const float4* w4 = (const float4*)w;
        for (int i = tid; i < 1536; i += 512) {
            int t4 = i & 3, rest = i >> 2;
            int ic = rest % 3, oc = rest / 3;
            float4 v = w4[(oc * 3 + ic) * 4 + t4];
            int base = ((t4 * 4) * 3 + ic) * 128 + oc;
            w_s[base + 0 * 3 * 128] = v.x;
            w_s[base + 1 * 3 * 128] = v.y;
            w_s[base + 2 * 3 * 128] = v.z;
            w_s[base + 3 * 3 * 128] = v.w;
        }
    }
    const int iy0 = 2 * Ty - 1, ix0 = 2 * Tx - 1;
    for (int i = tid; i < 3 * 19 * 67; i += 512) {
        int ic = i / (19 * 67), r = i % (19 * 67);
        int row = r / 67, col = r % 67;
        int gy = iy0 + row, gx = ix0 + col;
        float v = 0.f;
        if (gy >= 0 && gy < 256 && gx >= 0 && gx < 256)
            v = x[((n * 3 + ic) * 256 + gy) * 256 + gx];
        in_s[(ic * 19 + row) * 96 + (col & 1) * 48 + (col >> 1)] = v;
    }
    __syncthreads();

    u64 acc[4][8];
#pragma unroll
    for (int pp = 0; pp < 4; pp++)
#pragma unroll
        for (int k = 0; k < 8; k++) acc[pp][k] = 0ull;

    for (int ic = 0; ic < 3; ic++) {
#pragma unroll
        for (int ky = 0; ky < 4; ky++) {
#pragma unroll
            for (int kx = 0; kx < 4; kx++) {
                const ulonglong2* wp =
                    (const ulonglong2*)&w_s[((ky * 4 + kx) * 3 + ic) * 128 + oc16];
                ulonglong2 w0 = wp[0], w1 = wp[1], w2 = wp[2], w3 = wp[3];
                int coff = (kx & 1) * 48 + lane + (kx >> 1);
#pragma unroll
                for (int pp = 0; pp < 4; pp++) {
                    int tr = 2 * rw + 4 * pp + ky;
                    u64 iv = bcast2(in_s[(ic * 19 + tr) * 96 + coff]);
                    fma2(acc[pp][0], iv, w0.x); fma2(acc[pp][1], iv, w0.y);
                    fma2(acc[pp][2], iv, w1.x); fma2(acc[pp][3], iv, w1.y);
                    fma2(acc[pp][4], iv, w2.x); fma2(acc[pp][5], iv, w2.y);
                    fma2(acc[pp][6], iv, w3.x); fma2(acc[pp][7], iv, w3.y);
                }
            }
        }
    }
    const int ox = Tx + lane;
#pragma unroll
    for (int pp = 0; pp < 4; pp++) {
        int oy = Ty + rw + 2 * pp;
#pragma unroll
        for (int k = 0; k < 8; k++) {
            float2 v = unpack2(acc[pp][k]);
            int oc = oc16 + 2 * k;
            g_big[((n * 128 + oc) * 128 + oy) * 128 + ox]     = fmaxf(v.x + b[oc], 0.f);
            g_big[((n * 128 + oc + 1) * 128 + oy) * 128 + ox] = fmaxf(v.y + b[oc + 1], 0.f);
        }
    }
}

// ===========================================================================
// conv2 v2: z1 NCHW * enc_w2(64,128,4,4) s2 p1 + b -> g_z NHWC
// tile 32 cols x 16 rows, grid (2,4,32), block 512.
// warp = output row r (0..15); lane = t(0..3)*8+og: 8 px (ox=Tx+8t+j), 8 oc.
// A loaded as 12-float registers per (ic,row,parity); compile-time picks.
// ===========================================================================
__global__ void __launch_bounds__(512) k_conv2(const float* __restrict__ w,
                                               const float* __restrict__ b) {
    extern __shared__ float sm[];
    float* in_s = sm;            // 4*35*96 = 13440
    float* w_s = sm + 13440;     // 16*4*64 = 4096
    const int n = blockIdx.z;
    const int Tx = blockIdx.x * 32, Ty = blockIdx.y * 16;
    const int tid = threadIdx.x;
    const int lane = tid & 31;
    const int r = tid >> 5;                 // output row 0..15
    const int og = lane & 7, t = lane >> 3; // oc group, px octet
    const int ocb = og * 8;
    const int iy0 = 2 * Ty - 1, ix0 = 2 * Tx - 1;

    float bia[8];
    {
        const float4* b4 = (const float4*)(b + ocb);
        float4 b0 = b4[0], b1 = b4[1];
        bia[0]=b0.x; bia[1]=b0.y; bia[2]=b0.z; bia[3]=b0.w;
        bia[4]=b1.x; bia[5]=b1.y; bia[6]=b1.z; bia[7]=b1.w;
    }

    u64 acc[8][4];
#pragma unroll
    for (int j = 0; j < 8; j++)
#pragma unroll
        for (int k = 0; k < 4; k++) acc[j][k] = 0ull;

    const float4* w4 = (const float4*)w;
    for (int cc = 0; cc < 32; cc++) {
        __syncthreads();
        for (int i = tid; i < 1024; i += 512) {
            int t4 = i & 3, ic4 = (i >> 2) & 3, oc = i >> 4;
            float4 v = w4[(oc * 128 + cc * 4 + ic4) * 4 + t4];
            int base = ((t4 * 4) * 4 + ic4) * 64 + oc;
            w_s[base + 0 * 4 * 64] = v.x;
            w_s[base + 1 * 4 * 64] = v.y;
            w_s[base + 2 * 4 * 64] = v.z;
            w_s[base + 3 * 4 * 64] = v.w;
        }
        for (int i = tid; i < 4 * 35 * 67; i += 512) {
            int ic4 = i / (35 * 67), rr = i % (35 * 67);
            int row = rr / 67, col = rr % 67;
            int gy = iy0 + row, gx = ix0 + col;
            float v = 0.f;
            if (gy >= 0 && gy < 128 && gx >= 0 && gx < 128)
                v = g_big[((n * 128 + cc * 4 + ic4) * 128 + gy) * 128 + gx];
            in_s[(ic4 * 35 + row) * 96 + (col & 1) * 48 + (col >> 1)] = v;
        }
        __syncthreads();

        for (int ic4 = 0; ic4 < 4; ic4++) {
#pragma unroll
            for (int ky = 0; ky < 4; ky++) {
                int row = 2 * r + ky;
                int base = (ic4 * 35 + row) * 96 + 8 * t;
                const float4* pe = (const float4*)&in_s[base];
                const float4* po = (const float4*)&in_s[base + 48];
                float4 E0 = pe[0], E1 = pe[1], E2 = pe[2];
                float4 O0 = po[0], O1 = po[1], O2 = po[2];
                float e[12], o[12];
                e[0]=E0.x; e[1]=E0.y; e[2]=E0.z; e[3]=E0.w;
                e[4]=E1.x; e[5]=E1.y; e[6]=E1.z; e[7]=E1.w;
                e[8]=E2.x; e[9]=E2.y; e[10]=E2.z; e[11]=E2.w;
                o[0]=O0.x; o[1]=O0.y; o[2]=O0.z; o[3]=O0.w;
                o[4]=O1.x; o[5]=O1.y; o[6]=O1.z; o[7]=O1.w;
                o[8]=O2.x; o[9]=O2.y; o[10]=O2.z; o[11]=O2.w;
#pragma unroll
                for (int kx = 0; kx < 4; kx++) {
                    const int sh = kx >> 1;
                    const float4* wp =
                        (const float4*)&w_s[((ky * 4 + kx) * 4 + ic4) * 64 + ocb];
                    float4 wa = wp[0], wb = wp[1];
                    u64 W0 = pack2(wa.x, wa.y), W1 = pack2(wa.z, wa.w);
                    u64 W2 = pack2(wb.x, wb.y), W3 = pack2(wb.z, wb.w);
#pragma unroll
                    for (int j = 0; j < 8; j++) {
                        float av = (kx & 1) ? o[j + sh] : e[j + sh];
                        u64 a2 = bcast2(av);
                        fma2(acc[j][0], a2, W0); fma2(acc[j][1], a2, W1);
                        fma2(acc[j][2], a2, W2); fma2(acc[j][3], a2, W3);
                    }
                }
            }
        }
    }
    const int oy = Ty + r;
#pragma unroll
    for (int j = 0; j < 8; j++) {
        int ox = Tx + 8 * t + j;
        float4* zp = (float4*)&g_z[((n * 64 + oy) * 64 + ox) * 64 + ocb];
        float2 p0 = unpack2(acc[j][0]), p1 = unpack2(acc[j][1]);
        float2 p2 = unpack2(acc[j][2]), p3 = unpack2(acc[j][3]);
        float4 v0, v1;
        v0.x = p0.x + bia[0]; v0.y = p0.y + bia[1];
        v0.z = p1.x + bia[2]; v0.w = p1.y + bia[3];
        v1.x = p2.x + bia[4]; v1.y = p2.y + bia[5];
        v1.z = p3.x + bia[6]; v1.w = p3.y + bia[7];
        zp[0] = v0; zp[1] = v1;
    }
}

// ===========================================================================
// VQ (unchanged from R6 pass)
// ===========================================================================
__global__ void __launch_bounds__(256) k_vq(const float* __restrict__ cb) {
    extern __shared__ float sm[];
    float* cb_s = sm;               // 512*64
    float* ccn = sm + 32768;        // 512
    float* red = ccn + 512;         // 256
    const int tid = threadIdx.x;

    for (int i = tid; i < 32768; i += 256) cb_s[i] = cb[i];
    __syncthreads();
    for (int j = tid; j < 512; j += 256) {
        float s = 0.f;
        const float* cp = &cb_s[j * 64];
        for (int d = 0; d < 64; d++) s = fmaf(cp[d], cp[d], s);
        ccn[j] = s;
    }
    __syncthreads();

    const int i = blockIdx.x * 256 + tid;
    u64 zr[32];
    {
        const ulonglong2* zp = (const ulonglong2*)&g_z[(size_t)i * 64];
#pragma unroll
        for (int d = 0; d < 16; d++) {
            ulonglong2 tt = zp[d];
            zr[2 * d] = tt.x; zr[2 * d + 1] = tt.y;
        }
    }

    float best = 3.4e38f;
    int bi = 0;
    for (int j = 0; j < 512; j++) {
        const ulonglong2* cp = (const ulonglong2*)&cb_s[j * 64];
        u64 s2 = 0ull;
#pragma unroll
        for (int d = 0; d < 16; d++) {
            ulonglong2 c = cp[d];
            fma2(s2, zr[2 * d], c.x);
            fma2(s2, zr[2 * d + 1], c.y);
        }
        float2 ss = unpack2(s2);
        float score = ccn[j] - 2.f * (ss.x + ss.y);
        if (score < best) { best = score; bi = j; }
    }

    float4* qp = (float4*)&g_q[(size_t)i * 64];
    const float4* cp4 = (const float4*)&cb_s[bi * 64];
    const float4* zp4 = (const float4*)&g_z[(size_t)i * 64];
    float sq = 0.f;
#pragma unroll
    for (int d = 0; d < 16; d++) {
        float4 c = cp4[d], z = zp4[d];
        qp[d] = c;
        float dx = c.x - z.x, dy = c.y - z.y;
        float dz = c.z - z.z, dw = c.w - z.w;
        sq += dx * dx + dy * dy + dz * dz + dw * dw;
    }
    red[tid] = sq;
    __syncthreads();
    for (int st = 128; st > 0; st >>= 1) {
        if (tid < st) red[tid] += red[tid + st];
        __syncthreads();
    }
    if (tid == 0) g_part[blockIdx.x] = red[0];
}

// ===========================================================================
// deconv1 v2: q NHWC ^T-conv dec_w1(64,128,4,4) s2 p1 + b, ReLU -> h NHWC
// tile 32 cols x 8 rows, grid (4,16,32), block 512.
// warp = (r 0..7, h 0..1); lane = po(0..3)*8+og: c=po&1, t=po>>1.
// thread: 8 px (ox = Tx + c + 16t + 2j) x 8 oc (h*64+og*8).
// input stored in 2 parity-shifted planes: plane p, col' = col - p, stride 20.
// ===========================================================================
__global__ void __launch_bounds__(512) k_deconv1(const float* __restrict__ w,
                                                 const float* __restrict__ b) {
    extern __shared__ float sm[];
    float* in2 = sm;             // 2*8*6*20 = 1920
    float* w_s = sm + 1920;      // 16*1060 = 16960
    const int n = blockIdx.z;
    const int Tx = blockIdx.x * 32, Ty = blockIdx.y * 8;
    const int tid = threadIdx.x;
    const int lane = tid & 31, wid = tid >> 5;
    const int r = wid & 7, h = wid >> 3;
    const int og = lane & 7, po = lane >> 3;
    const int c = po & 1, t = po >> 1;
    const int ocb = h * 64 + og * 8;

    const int oy = Ty + r;
    const int ky0 = (r + 1) & 1;
    const int fl = (r + 1) >> 1;            // floor((r+1)/2), in 0..4
    const int kx0 = (c + 1) & 1;
    const int y0 = (Ty >> 1) - 1, x0 = (Tx >> 1) - 1;

    float bia[8];
    {
        const float4* b4 = (const float4*)(b + ocb);
        float4 b0 = b4[0], b1 = b4[1];
        bia[0]=b0.x; bia[1]=b0.y; bia[2]=b0.z; bia[3]=b0.w;
        bia[4]=b1.x; bia[5]=b1.y; bia[6]=b1.z; bia[7]=b1.w;
    }

    u64 acc[8][4];
#pragma unroll
    for (int j = 0; j < 8; j++)
#pragma unroll
        for (int k = 0; k < 4; k++) acc[j][k] = 0ull;

    const int abase0 = c * 960 + 8 * t;     // + ic8*120 + row*20

    const float4* w4 = (const float4*)w;
    for (int cc = 0; cc < 8; cc++) {
        __syncthreads();
        // weights: w_s[tap*1060 + ic8*132 + oc] = w[((cc*8+ic8)*128+oc)*16+tap]
        for (int i = tid; i < 4096; i += 512) {
            int t4 = i & 3, oc = (i >> 2) & 127, ic8 = i >> 9;
            float4 v = w4[((cc * 8 + ic8) * 128 + oc) * 4 + t4];
            int base = (t4 * 4) * 1060 + ic8 * 132 + oc;
            w_s[base + 0 * 1060] = v.x;
            w_s[base + 1 * 1060] = v.y;
            w_s[base + 2 * 1060] = v.z;
            w_s[base + 3 * 1060] = v.w;
        }
        // input: two parity-shifted planes [p][ic8][row][col'], col = col' + p
        for (int i = tid; i < 1920; i += 512) {
            int p = i / 960, rem = i % 960;
            int ic8 = rem / 120, rem2 = rem % 120;
            int row = rem2 / 20, colp = rem2 % 20;
            int col = colp + p;
            int gy = y0 + row, gx = x0 + col;
            float v = 0.f;
            if (col <= 17 && gy >= 0 && gy < 64 && gx >= 0 && gx < 64)
                v = g_q[(((size_t)n * 64 + gy) * 64 + gx) * 64 + cc * 8 + ic8];
            in2[i] = v;
        }
        __syncthreads();

        for (int ic8 = 0; ic8 < 8; ic8++) {
            // A windows: row fl+1 (ty=0) and row fl (ty=1), 12 floats each
            const float4* a0p = (const float4*)&in2[abase0 + ic8 * 120 + (fl + 1) * 20];
            const float4* a1p = (const float4*)&in2[abase0 + ic8 * 120 + fl * 20];
            float4 A0 = a0p[0], A1 = a0p[1], A2 = a0p[2];
            float4 B0 = a1p[0], B1 = a1p[1], B2 = a1p[2];
            float ea[12], fa[12];
            ea[0]=A0.x; ea[1]=A0.y; ea[2]=A0.z; ea[3]=A0.w;
            ea[4]=A1.x; ea[5]=A1.y; ea[6]=A1.z; ea[7]=A1.w;
            ea[8]=A2.x; ea[9]=A2.y; ea[10]=A2.z; ea[11]=A2.w;
            fa[0]=B0.x; fa[1]=B0.y; fa[2]=B0.z; fa[3]=B0.w;
            fa[4]=B1.x; fa[5]=B1.y; fa[6]=B1.z; fa[7]=B1.w;
            fa[8]=B2.x; fa[9]=B2.y; fa[10]=B2.z; fa[11]=B2.w;
#pragma unroll
            for (int ty = 0; ty < 2; ty++) {
                int ky = ky0 + 2 * ty;
#pragma unroll
                for (int tx = 0; tx < 2; tx++) {
                    int kx = kx0 + 2 * tx;
                    const float4* wp =
                        (const float4*)&w_s[(ky * 4 + kx) * 1060 + ic8 * 132 + ocb];
                    float4 wa = wp[0], wb = wp[1];
                    u64 W0 = pack2(wa.x, wa.y), W1 = pack2(wa.z, wa.w);
                    u64 W2 = pack2(wb.x, wb.y), W3 = pack2(wb.z, wb.w);
#pragma unroll
                    for (int j = 0; j < 8; j++) {
                        float av = ty ? fa[j + 1 - tx] : ea[j + 1 - tx];
                        u64 a2 = bcast2(av);
                        fma2(acc[j][0], a2, W0); fma2(acc[j][1], a2, W1);
                        fma2(acc[j][2], a2, W2); fma2(acc[j][3], a2, W3);
                    }
                }
            }
        }
    }
#pragma unroll
    for (int j = 0; j < 8; j++) {
        int ox = Tx + c + 16 * t + 2 * j;
        float4* hp = (float4*)&g_big[(((size_t)n * 128 + oy) * 128 + ox) * 128 + ocb];
        float2 p0 = unpack2(acc[j][0]), p1 = unpack2(acc[j][1]);
        float2 p2 = unpack2(acc[j][2]), p3 = unpack2(acc[j][3]);
        float4 v0, v1;
        v0.x = fmaxf(p0.x + bia[0], 0.f); v0.y = fmaxf(p0.y + bia[1], 0.f);
        v0.z = fmaxf(p1.x + bia[2], 0.f); v0.w = fmaxf(p1.y + bia[3], 0.f);
        v1.x = fmaxf(p2.x + bia[4], 0.f); v1.y = fmaxf(p2.y + bia[5], 0.f);
        v1.z = fmaxf(p3.x + bia[6], 0.f); v1.w = fmaxf(p3.y + bia[7], 0.f);
        hp[0] = v0; hp[1] = v1;
    }
}

// ===========================================================================
// deconv2 (unchanged from R6 pass)
// ===========================================================================
__global__ void __launch_bounds__(256) k_deconv2(const float* __restrict__ w,
                                                 const float* __restrict__ b,
                                                 float* __restrict__ out) {
    extern __shared__ float sm[];
    float* in_s = sm;             // 180*132 = 23760
    float* w_s = sm + 23760;      // 6144
    const int n = blockIdx.z;
    const int Tx = blockIdx.x * 32, Ty = blockIdx.y * 16;
    const int tid = threadIdx.x;
    const int py = tid >> 4, px = tid & 15;
    const int oy = Ty + py, ox = Tx + px;
    const int y0 = (Ty >> 1) - 1, x0 = (Tx >> 1) - 1;

    {
        const float4* w4 = (const float4*)w;
        for (int i = tid; i < 1536; i += 256) {
            int t4 = i & 3, rest = i >> 2;
            int oc = rest % 3, ic = rest / 3;
            float4 v = w4[(ic * 3 + oc) * 4 + t4];
            int base = ((t4 * 4) * 3 + oc) * 128 + ic;
            w_s[base + 0 * 3 * 128] = v.x;
            w_s[base + 1 * 3 * 128] = v.y;
            w_s[base + 2 * 3 * 128] = v.z;
            w_s[base + 3 * 3 * 128] = v.w;
        }
    }
    for (int i = tid; i < 23040; i += 256) {
        int ic = i & 127, pos = i >> 7;
        int ly = pos / 18, lx = pos % 18;
        int gy = y0 + ly, gx = x0 + lx;
        float v = 0.f;
        if (gy >= 0 && gy < 128 && gx >= 0 && gx < 128)
            v = g_big[(((size_t)n * 128 + gy) * 128 + gx) * 128 + ic];
        in_s[pos * 132 + ic] = v;
    }
    __syncthreads();

    const int ky0 = (oy + 1) & 1, kx0 = (ox + 1) & 1;
    const int lyA = ((oy + 1 - ky0) >> 1) - y0;
    const int lxA = ((ox + 1 - kx0) >> 1) - x0;

    u64 a[2][3];
#pragma unroll
    for (int q = 0; q < 2; q++)
#pragma unroll
        for (int k = 0; k < 3; k++) a[q][k] = 0ull;

#pragma unroll
    for (int ty = 0; ty < 2; ty++) {
        int ky = ky0 + 2 * ty, ly = lyA - ty;
#pragma unroll
        for (int tx = 0; tx < 2; tx++) {
            int kx = kx0 + 2 * tx;
            const ulonglong2* ip0 = (const ulonglong2*)&in_s[(ly * 18 + lxA - tx) * 132];
            const ulonglong2* ip1 = (const ulonglong2*)&in_s[(ly * 18 + lxA + 8 - tx) * 132];
            const ulonglong2* w0 = (const ulonglong2*)&w_s[((ky * 4 + kx) * 3 + 0) * 128];
            const ulonglong2* w1 = (const ulonglong2*)&w_s[((ky * 4 + kx) * 3 + 1) * 128];
            const ulonglong2* w2 = (const ulonglong2*)&w_s[((ky * 4 + kx) * 3 + 2) * 128];
#pragma unroll 8
            for (int cI = 0; cI < 32; cI++) {
                ulonglong2 v0 = w0[cI], v1 = w1[cI], v2 = w2[cI];
                ulonglong2 i0 = ip0[cI], i1 = ip1[cI];
                fma2(a[0][0], i0.x, v0.x); fma2(a[0][0], i0.y, v0.y);
                fma2(a[0][1], i0.x, v1.x); fma2(a[0][1], i0.y, v1.y);
                fma2(a[0][2], i0.x, v2.x); fma2(a[0][2], i0.y, v2.y);
                fma2(a[1][0], i1.x, v0.x); fma2(a[1][0], i1.y, v0.y);
                fma2(a[1][1], i1.x, v1.x); fma2(a[1][1], i1.y, v1.y);
                fma2(a[1][2], i1.x, v2.x); fma2(a[1][2], i1.y, v2.y);
            }
        }
    }
#pragma unroll
    for (int q = 0; q < 2; q++) {
        int oxq = ox + 16 * q;
        float2 r0 = unpack2(a[q][0]), r1 = unpack2(a[q][1]), r2 = unpack2(a[q][2]);
        out[(((size_t)n * 3 + 0) * 256 + oy) * 256 + oxq] = tanhf(r0.x + r0.y + b[0]);
        out[(((size_t)n * 3 + 1) * 256 + oy) * 256 + oxq] = tanhf(r1.x + r1.y + b[1]);
        out[(((size_t)n * 3 + 2) * 256 + oy) * 256 + oxq] = tanhf(r2.x + r2.y + b[2]);
    }
}

// deterministic loss finalize: vq_loss = 1.25 * sum / (131072*64)
__global__ void k_loss(float* __restrict__ out, int out_size) {
    __shared__ float red[256];
    int tid = threadIdx.x;
    red[tid] = g_part[tid] + g_part[tid + 256];
    __syncthreads();
    for (int st = 128; st > 0; st >>= 1) {
        if (tid < st) red[tid] += red[tid + st];
        __syncthreads();
    }
    if (tid == 0) out[out_size - 1] = 1.25f * red[0] / 8388608.0f;
}

extern "C" void kernel_launch(void* const* d_in, const int* in_sizes, int n_in,
                              void* d_out, int out_size) {
    const float* x   = (const float*)d_in[0];
    const float* ew1 = (const float*)d_in[1];
    const float* eb1 = (const float*)d_in[2];
    const float* ew2 = (const float*)d_in[3];
    const float* eb2 = (const float*)d_in[4];
    const float* cb  = (const float*)d_in[5];
    const float* dw1 = (const float*)d_in[6];
    const float* db1 = (const float*)d_in[7];
    const float* dw2 = (const float*)d_in[8];
    const float* db2 = (const float*)d_in[9];
    float* out = (float*)d_out;

    const int smem_conv2   = (13440 + 4096) * 4;   // 70144
    const int smem_vq      = (32768 + 512 + 256) * 4;
    const int smem_deconv1 = (1920 + 16960) * 4;   // 75520
    const int smem_deconv2 = (23760 + 6144) * 4;

    cudaFuncSetAttribute(k_conv2, cudaFuncAttributeMaxDynamicSharedMemorySize, smem_conv2);
    cudaFuncSetAttribute(k_vq, cudaFuncAttributeMaxDynamicSharedMemorySize, smem_vq);
    cudaFuncSetAttribute(k_deconv1, cudaFuncAttributeMaxDynamicSharedMemorySize, smem_deconv1);
    cudaFuncSetAttribute(k_deconv2, cudaFuncAttributeMaxDynamicSharedMemorySize, smem_deconv2);

    k_conv1<<<dim3(4, 16, 32), 512>>>(x, ew1, eb1);
    k_conv2<<<dim3(2, 4, 32), 512, smem_conv2>>>(ew2, eb2);
    k_vq<<<512, 256, smem_vq>>>(cb);
    k_deconv1<<<dim3(4, 16, 32), 512, smem_deconv1>>>(dw1, db1);
    k_deconv2<<<dim3(8, 16, 32), 256, smem_deconv2>>>(dw2, db2, out);
    k_loss<<<1, 256>>>(out, out_size);
}